// round 2
// baseline (speedup 1.0000x reference)
#include <cuda_runtime.h>
#include <cuda_bf16.h>
#include <cstdint>

// ClusterDiceLoss — R2: warp-aggregated (match_any + ballot) histogram,
// zero atomics in the hot loop, single fused kernel (last-block finalize).
//
//   dice_s = 2*inter_s / max(sum_p_s + sum_t_s, 1)   (1.0 if union == 0)
//   out    = 1 - mean_s(dice_s),  s = 1..K
//
// Per-warp u64 histogram packs (sum_t | sum_p<<21 | inter<<42); counts per
// warp-bin < 2^21, global float sums < 2^24 -> exact, order-independent.

#define NSEG  65
#define WARPS 8
#define TPB   256

__device__ float    g_acc[3 * NSEG];   // zero-init at load; re-zeroed each call
__device__ unsigned g_done = 0;

__device__ __forceinline__ void slot_accum(int l, float p, float t,
                                           unsigned long long* __restrict__ whist,
                                           unsigned lane)
{
    bool pp = p > 0.0f;
    bool tt = t > 0.0f;
    unsigned mask = __match_any_sync(0xffffffffu, l);
    unsigned bp   = __ballot_sync(0xffffffffu, pp);
    unsigned bt   = __ballot_sync(0xffffffffu, tt);
    // group leader = lowest lane in matched group
    if (l > 0 && lane == (unsigned)(__ffs(mask) - 1)) {
        unsigned st = __popc(mask & bt);
        unsigned sp = __popc(mask & bp);
        unsigned it = __popc(mask & bp & bt);
        unsigned long long c = (unsigned long long)st
                             | ((unsigned long long)sp << 21)
                             | ((unsigned long long)it << 42);
        if (c) whist[l] += c;   // non-atomic: per-warp hist, distinct l per group
    }
}

__global__ void __launch_bounds__(TPB) fused_dice_kernel(
    const float4* __restrict__ pred4,
    const float4* __restrict__ targ4,
    const int4*   __restrict__ lab4,
    long long n4w,               // vec4 count rounded down to multiple of 32
    const float*  __restrict__ pred_s,
    const float*  __restrict__ targ_s,
    const int*    __restrict__ lab_s,
    long long n_total,
    const int*    __restrict__ num_clusters_p,
    float* __restrict__ out)
{
    __shared__ unsigned long long s_hist[WARPS][NSEG];
    __shared__ float sdice[64];
    __shared__ bool  s_last;

    int tid  = threadIdx.x;
    int wid  = tid >> 5;
    unsigned lane = tid & 31u;

    for (int i = tid; i < WARPS * NSEG; i += TPB)
        ((unsigned long long*)s_hist)[i] = 0ULL;
    __syncthreads();

    unsigned long long* whist = s_hist[wid];

    // Main loop: warp-uniform trip count (n4w multiple of 32, warp windows aligned)
    long long stride = (long long)gridDim.x * TPB;
    for (long long i = (long long)blockIdx.x * TPB + tid; i < n4w; i += stride) {
        int4   L = lab4[i];
        float4 P = pred4[i];
        float4 T = targ4[i];
        slot_accum(L.x, P.x, T.x, whist, lane);
        slot_accum(L.y, P.y, T.y, whist, lane);
        slot_accum(L.z, P.z, T.z, whist, lane);
        slot_accum(L.w, P.w, T.w, whist, lane);
    }

    // Tail (vec remainder + scalar remainder): block 0 only, shared atomics (tiny)
    if (blockIdx.x == 0) {
        for (long long i = n4w * 4 + tid; i < n_total; i += TPB) {
            int l  = lab_s[i];
            int pp = pred_s[i] > 0.0f;
            int tt = targ_s[i] > 0.0f;
            if (l > 0 && (pp | tt)) {
                unsigned long long c = (unsigned long long)tt
                                     | ((unsigned long long)pp << 21)
                                     | ((unsigned long long)(pp & tt) << 42);
                atomicAdd(&whist[l], c);
            }
        }
    }
    __syncthreads();

    // Flush block histogram to global float accumulators
    if (tid < NSEG) {
        unsigned long long v = 0ULL;
        #pragma unroll
        for (int w = 0; w < WARPS; w++) v += s_hist[w][tid];
        if (v) {
            const unsigned long long M21 = (1ULL << 21) - 1ULL;
            atomicAdd(&g_acc[tid],             (float)(v >> 42));        // inter
            atomicAdd(&g_acc[NSEG + tid],      (float)((v >> 21) & M21)); // sum_p
            atomicAdd(&g_acc[2 * NSEG + tid],  (float)(v & M21));         // sum_t
        }
    }
    __threadfence();
    __syncthreads();

    if (tid == 0) {
        unsigned r = atomicAdd(&g_done, 1u);
        s_last = (r == (unsigned)(gridDim.x - 1));
    }
    __syncthreads();

    if (s_last) {
        __threadfence();   // acquire: all blocks' flush atomics visible
        if (tid < 64) {
            volatile float* ga = g_acc;
            int s = tid + 1;
            float it = ga[s];
            float sp = ga[NSEG + s];
            float st = ga[2 * NSEG + s];
            float u  = sp + st;
            sdice[tid] = (u > 0.0f) ? (2.0f * it / fmaxf(u, 1.0f)) : 1.0f;
        }
        __syncthreads();
        if (tid == 0) {
            float sum = 0.0f;
            #pragma unroll
            for (int i = 0; i < 64; i++) sum += sdice[i];
            out[0] = 1.0f - sum / (float)(*num_clusters_p);
        }
        // Reset state for next graph replay (reads of g_acc are all done above)
        if (tid < 3 * NSEG) g_acc[tid] = 0.0f;
        __threadfence();
        if (tid == 0) g_done = 0u;
    }
}

extern "C" void kernel_launch(void* const* d_in, const int* in_sizes, int n_in,
                              void* d_out, int out_size) {
    const float* pred   = (const float*)d_in[0];
    const float* target = (const float*)d_in[1];
    const int*   labels = (const int*)d_in[2];
    const int*   numcl  = (const int*)d_in[3];
    float* out = (float*)d_out;

    long long n   = (long long)in_sizes[0];
    long long n4  = n >> 2;
    long long n4w = n4 & ~31LL;

    int blocks = 148 * 8;   // full occupancy at 256 thr/block
    fused_dice_kernel<<<blocks, TPB>>>(
        (const float4*)pred, (const float4*)target, (const int4*)labels, n4w,
        pred, target, labels, n, numcl, out);
}